// round 3
// baseline (speedup 1.0000x reference)
#include <cuda_runtime.h>
#include <math.h>

#define BB 8
#define SEQL 256
#define MEML 768
#define TOT 1024
#define DIMM 512
#define NH 8
#define DH 64
#define INNERD 512
#define CTXL 1024
#define NOCTL 11

typedef unsigned long long u64p;   // packed f32x2

__device__ __forceinline__ u64p fbcast(float x) {
    u64p r; asm("mov.b64 %0, {%1, %1};" : "=l"(r) : "f"(x)); return r;
}
__device__ __forceinline__ void ffma2(u64p& d, u64p a, u64p b) {
    asm("fma.rn.f32x2 %0, %1, %2, %0;" : "+l"(d) : "l"(a), "l"(b));
}
__device__ __forceinline__ void fmul2(u64p& d, u64p a) {
    asm("mul.rn.f32x2 %0, %0, %1;" : "+l"(d) : "l"(a));
}
__device__ __forceinline__ float2 funpack(u64p v) {
    float2 r; asm("mov.b64 {%0, %1}, %2;" : "=f"(r.x), "=f"(r.y) : "l"(v)); return r;
}

// ---------------- scratch (device globals; no allocation allowed) ----------------
__device__ float g_QU[BB*NH*SEQL*DH];           // q + u_emb   (4 MB)
__device__ float g_QV[BB*NH*SEQL*DH];           // q + v_emb   (4 MB)
__device__ float g_K [(size_t)BB*NH*TOT*DH];    // 16 MB
__device__ float g_V [(size_t)BB*NH*TOT*DH];    // 16 MB
__device__ float g_Krel[NH*CTXL*DH];            // (R @ W_rel) as [h][s][d]  (2 MB)
__device__ float g_BD[(size_t)BB*NH*SEQL*CTXL]; // qv . Krel^T  (64 MB)
__device__ float g_AO[BB*SEQL*INNERD];          // attention output, [b][n][h*64+d] (4 MB)

// =====================================================================
// Kernel 1: QKV projection.  C[8192 x 1536] = concat(memory,x)[8192 x 512] @ W_qkv
// 128x128 tile, BK=16, 256 threads, 8x8 micro-tile in f32x2 pairs.
// =====================================================================
__global__ __launch_bounds__(256) void qkv_kernel(
    const float* __restrict__ x, const float* __restrict__ mm,
    const float* __restrict__ W, const float* __restrict__ u_emb,
    const float* __restrict__ v_emb)
{
    __shared__ __align__(16) float AsT[16][132];  // [k][row]
    __shared__ __align__(16) float Bs [16][132];  // [k][col]
    int t  = threadIdx.x;
    int tx = t & 15, ty = t >> 4;
    int r0 = blockIdx.y * 128;
    int c0 = blockIdx.x * 128;

    u64p acc2[8][4];
#pragma unroll
    for (int i = 0; i < 8; i++)
#pragma unroll
        for (int j = 0; j < 4; j++) acc2[i][j] = 0ull;

    for (int k0 = 0; k0 < DIMM; k0 += 16) {
        __syncthreads();
#pragma unroll
        for (int q = 0; q < 2; q++) {
            int fid = t*2 + q;
            int rr = fid >> 2, k4 = fid & 3;
            int gr = r0 + rr;
            int b = gr >> 10, pos = gr & 1023;
            const float* src = (pos < MEML)
                ? (mm + ((size_t)(b*MEML + pos))*DIMM)
                : (x  + ((size_t)(b*SEQL + pos - MEML))*DIMM);
            float4 v = *(const float4*)(src + k0 + k4*4);
            AsT[k4*4+0][rr] = v.x; AsT[k4*4+1][rr] = v.y;
            AsT[k4*4+2][rr] = v.z; AsT[k4*4+3][rr] = v.w;
        }
#pragma unroll
        for (int q = 0; q < 2; q++) {
            int fid = t*2 + q;
            int kk = fid >> 5, c4 = fid & 31;
            *(float4*)&Bs[kk][c4*4] =
                *(const float4*)(W + (size_t)(k0+kk)*1536 + c0 + c4*4);
        }
        __syncthreads();
#pragma unroll
        for (int kk = 0; kk < 16; kk++) {
            float4 a0 = *(float4*)&AsT[kk][ty*8];
            float4 a1 = *(float4*)&AsT[kk][ty*8+4];
            u64p ar[8];
            ar[0]=fbcast(a0.x); ar[1]=fbcast(a0.y); ar[2]=fbcast(a0.z); ar[3]=fbcast(a0.w);
            ar[4]=fbcast(a1.x); ar[5]=fbcast(a1.y); ar[6]=fbcast(a1.z); ar[7]=fbcast(a1.w);
            ulonglong2 bb0 = *(const ulonglong2*)&Bs[kk][tx*8];
            ulonglong2 bb1 = *(const ulonglong2*)&Bs[kk][tx*8+4];
            u64p br[4] = {bb0.x, bb0.y, bb1.x, bb1.y};
#pragma unroll
            for (int i = 0; i < 8; i++)
#pragma unroll
                for (int j = 0; j < 4; j++) ffma2(acc2[i][j], ar[i], br[j]);
        }
    }

#pragma unroll
    for (int i = 0; i < 8; i++) {
        int gr = r0 + ty*8 + i;
        int b = gr >> 10, pos = gr & 1023;
        float accr[8];
#pragma unroll
        for (int j = 0; j < 4; j++) {
            float2 p = funpack(acc2[i][j]);
            accr[2*j] = p.x; accr[2*j+1] = p.y;
        }
#pragma unroll
        for (int j = 0; j < 8; j++) {
            int c = c0 + tx*8 + j;
            int which = c >> 9;       // 0=q, 1=k, 2=v
            int cc = c & 511;
            int h = cc >> 6, d = cc & 63;
            float val = accr[j];
            if (which == 1) {
                g_K[(((size_t)(b*NH + h))*TOT + pos)*DH + d] = val;
            } else if (which == 2) {
                g_V[(((size_t)(b*NH + h))*TOT + pos)*DH + d] = val;
            } else if (pos >= MEML) {
                int n = pos - MEML;
                size_t idx = (((size_t)(b*NH + h))*SEQL + n)*DH + d;
                g_QU[idx] = val + u_emb[d];
                g_QV[idx] = val + v_emb[d];
            }
        }
    }
}

// =====================================================================
// Kernel 2: Krel[s, h, d] = (posenc(s) @ W_rel), stored [h][s][d]
// =====================================================================
__global__ __launch_bounds__(512) void krel_kernel(const float* __restrict__ Wrel)
{
    __shared__ float R[2*NOCTL];
    int s = blockIdx.x;
    int t = threadIdx.x;
    if (t < NOCTL) {
        float mult = exp2f((float)(t - (NOCTL-1))) * 3.14159265358979323846f;
        float arg = (float)s * mult;
        R[t]         = sinf(arg);
        R[t + NOCTL] = cosf(arg);
    }
    __syncthreads();
    float acc = 0.f;
#pragma unroll
    for (int j = 0; j < 2*NOCTL; j++) acc += R[j] * Wrel[j*INNERD + t];
    int h = t >> 6, d = t & 63;
    g_Krel[((size_t)h*CTXL + s)*DH + d] = acc;
}

// =====================================================================
// Kernel 3: BD[b,h,n,s] = QV[b,h,n,:] . Krel[h,s,:]   (NT GEMM, K=64)
// =====================================================================
__global__ __launch_bounds__(256) void bd_kernel()
{
    __shared__ __align__(16) float AsT[64][68];  // [d][n]
    __shared__ __align__(16) float BsT[64][68];  // [d][s]
    int t  = threadIdx.x;
    int tx = t & 15, ty = t >> 4;
    int bh = blockIdx.z;
    int h  = bh & 7;
    int n0 = blockIdx.y * 64;
    int s0 = blockIdx.x * 64;

    if (s0 > MEML + n0 + 63) return;   // never read by shifted access

    {
        int d4 = t & 15, row = t >> 4;
        const float* A  = g_QV   + ((size_t)bh*SEQL + n0)*DH;
        const float* Bk = g_Krel + ((size_t)h*CTXL + s0)*DH;
#pragma unroll
        for (int rr = row; rr < 64; rr += 16) {
            float4 a = *(const float4*)(A  + (size_t)rr*DH + d4*4);
            AsT[d4*4+0][rr] = a.x; AsT[d4*4+1][rr] = a.y;
            AsT[d4*4+2][rr] = a.z; AsT[d4*4+3][rr] = a.w;
            float4 b = *(const float4*)(Bk + (size_t)rr*DH + d4*4);
            BsT[d4*4+0][rr] = b.x; BsT[d4*4+1][rr] = b.y;
            BsT[d4*4+2][rr] = b.z; BsT[d4*4+3][rr] = b.w;
        }
    }
    __syncthreads();

    u64p acc2[4][2];
#pragma unroll
    for (int i = 0; i < 4; i++) { acc2[i][0] = 0ull; acc2[i][1] = 0ull; }

#pragma unroll
    for (int d = 0; d < 64; d++) {
        float4 a4 = *(float4*)&AsT[d][ty*4];
        ulonglong2 bb = *(const ulonglong2*)&BsT[d][tx*4];
        u64p ar[4] = {fbcast(a4.x), fbcast(a4.y), fbcast(a4.z), fbcast(a4.w)};
#pragma unroll
        for (int i = 0; i < 4; i++) {
            ffma2(acc2[i][0], ar[i], bb.x);
            ffma2(acc2[i][1], ar[i], bb.y);
        }
    }

    float* out = g_BD + ((size_t)bh*SEQL + n0)*CTXL + s0;
#pragma unroll
    for (int i = 0; i < 4; i++) {
        float2 p0 = funpack(acc2[i][0]);
        float2 p1 = funpack(acc2[i][1]);
        *(float4*)&out[(size_t)(ty*4+i)*CTXL + tx*4] = make_float4(p0.x, p0.y, p1.x, p1.y);
    }
}

// =====================================================================
// Kernel 4: flash attention, 32-query tiles (grid 512 -> occupancy), f32x2 math.
// smem: QT[64][36] + KT[64][68] + VT[64][68] + PT[32][68] = ~52.7KB
// =====================================================================
#define ATTN_SMEM_FLOATS (64*36 + 64*68 + 64*68 + 32*68)

__global__ __launch_bounds__(256) void attn_kernel()
{
    extern __shared__ float smem[];
    float* QT = smem;             // [d][n] stride 36
    float* KT = QT + 64*36;       // [d][m] stride 68
    float* VT = KT + 64*68;       // [m][d] stride 68
    float* PT = VT + 64*68;       // [n][m] stride 68

    int t  = threadIdx.x;
    int tx = t & 15, ty = t >> 4;
    int bh = blockIdx.y;
    int b  = bh >> 3, h = bh & 7;
    int n0 = blockIdx.x * 32;

    {   // load QU tile (32 x 64), transposed
        int d4 = t & 15, row = t >> 4;
        const float* Q = g_QU + ((size_t)bh*SEQL + n0)*DH;
#pragma unroll
        for (int rr = row; rr < 32; rr += 16) {
            float4 a = *(const float4*)(Q + (size_t)rr*DH + d4*4);
            QT[(d4*4+0)*36 + rr] = a.x; QT[(d4*4+1)*36 + rr] = a.y;
            QT[(d4*4+2)*36 + rr] = a.z; QT[(d4*4+3)*36 + rr] = a.w;
        }
    }

    u64p O2[2][2];
    float M[2], L[2];
    const float* bdp[2];
    int limit[2];
#pragma unroll
    for (int i = 0; i < 2; i++) {
        M[i] = -1e30f; L[i] = 0.f;
        int ng = n0 + ty*2 + i;
        limit[i] = MEML + ng;
        bdp[i] = g_BD + ((size_t)bh*SEQL + ng)*CTXL + limit[i];
        O2[i][0] = 0ull; O2[i][1] = 0ull;
    }

    int ntiles = (MEML + n0 + 31)/64 + 1;

    for (int tile = 0; tile < ntiles; tile++) {
        int m0 = tile * 64;
        __syncthreads();
        {   // K transposed + V natural
            int d4 = t & 15, row = t >> 4;
            const float* Kp = g_K + ((size_t)bh*TOT + m0)*DH;
            const float* Vp = g_V + ((size_t)bh*TOT + m0)*DH;
#pragma unroll
            for (int rr = row; rr < 64; rr += 16) {
                float4 a = *(const float4*)(Kp + (size_t)rr*DH + d4*4);
                KT[(d4*4+0)*68 + rr] = a.x; KT[(d4*4+1)*68 + rr] = a.y;
                KT[(d4*4+2)*68 + rr] = a.z; KT[(d4*4+3)*68 + rr] = a.w;
                *(float4*)&VT[rr*68 + d4*4] = *(const float4*)(Vp + (size_t)rr*DH + d4*4);
            }
        }
        __syncthreads();

        // S = QU . K^T  (2 rows x 4 cols per thread, f32x2 pairs)
        u64p Sp[2][2];
        Sp[0][0]=0ull; Sp[0][1]=0ull; Sp[1][0]=0ull; Sp[1][1]=0ull;
#pragma unroll 16
        for (int d = 0; d < 64; d++) {
            u64p a0 = fbcast(QT[d*36 + ty*2]);
            u64p a1 = fbcast(QT[d*36 + ty*2 + 1]);
            ulonglong2 bb = *(const ulonglong2*)&KT[d*68 + tx*4];
            ffma2(Sp[0][0], a0, bb.x); ffma2(Sp[0][1], a0, bb.y);
            ffma2(Sp[1][0], a1, bb.x); ffma2(Sp[1][1], a1, bb.y);
        }

#pragma unroll
        for (int i = 0; i < 2; i++) {
            float2 u0 = funpack(Sp[i][0]);
            float2 u1 = funpack(Sp[i][1]);
            float S[4] = {u0.x, u0.y, u1.x, u1.y};
            float mx = -1e30f;
#pragma unroll
            for (int j = 0; j < 4; j++) {
                int m = m0 + tx*4 + j;
                S[j] = (m <= limit[i]) ? (S[j] + bdp[i][-m]) * 0.125f : -1e30f;
                mx = fmaxf(mx, S[j]);
            }
#pragma unroll
            for (int off = 8; off; off >>= 1)
                mx = fmaxf(mx, __shfl_xor_sync(0xffffffffu, mx, off));
            float Mn = fmaxf(M[i], mx);
            float alpha = __expf(M[i] - Mn);
            M[i] = Mn;
            float s = 0.f;
#pragma unroll
            for (int j = 0; j < 4; j++) {
                float p = __expf(S[j] - Mn);
                S[j] = p;
                s += p;
            }
#pragma unroll
            for (int off = 8; off; off >>= 1)
                s += __shfl_xor_sync(0xffffffffu, s, off);
            L[i] = L[i]*alpha + s;
            u64p al = fbcast(alpha);
            fmul2(O2[i][0], al); fmul2(O2[i][1], al);
            *(float4*)&PT[(ty*2+i)*68 + tx*4] = make_float4(S[0], S[1], S[2], S[3]);
        }
        __syncthreads();

        // O += P . V
#pragma unroll 8
        for (int mmm = 0; mmm < 64; mmm++) {
            u64p p0 = fbcast(PT[(ty*2  )*68 + mmm]);
            u64p p1 = fbcast(PT[(ty*2+1)*68 + mmm]);
            ulonglong2 v2 = *(const ulonglong2*)&VT[mmm*68 + tx*4];
            ffma2(O2[0][0], p0, v2.x); ffma2(O2[0][1], p0, v2.y);
            ffma2(O2[1][0], p1, v2.x); ffma2(O2[1][1], p1, v2.y);
        }
    }

#pragma unroll
    for (int i = 0; i < 2; i++) {
        int ng = n0 + ty*2 + i;
        float r = 1.f / L[i];
        float2 o0 = funpack(O2[i][0]);
        float2 o1 = funpack(O2[i][1]);
        *(float4*)&g_AO[((size_t)(b*SEQL + ng))*INNERD + h*DH + tx*4] =
            make_float4(o0.x*r, o0.y*r, o1.x*r, o1.y*r);
    }
}

// =====================================================================
// Kernel 5: out = AO[2048 x 512] @ W_out[512 x 512] + b_out
// =====================================================================
__global__ __launch_bounds__(256) void out_kernel(
    const float* __restrict__ W, const float* __restrict__ bias,
    float* __restrict__ out)
{
    __shared__ __align__(16) float AsT[32][68];
    __shared__ __align__(16) float Bs [32][68];
    int t  = threadIdx.x;
    int tx = t & 15, ty = t >> 4;
    int r0 = blockIdx.y * 64;
    int c0 = blockIdx.x * 64;

    u64p acc2[4][2];
#pragma unroll
    for (int i = 0; i < 4; i++) { acc2[i][0] = 0ull; acc2[i][1] = 0ull; }

    for (int k0 = 0; k0 < INNERD; k0 += 32) {
        {
            int k4  = t & 7;
            int row = t >> 3;
#pragma unroll
            for (int rr = row; rr < 64; rr += 32) {
                int gr = r0 + rr;
                float4 v = *(const float4*)(g_AO + (size_t)gr*INNERD + k0 + k4*4);
                AsT[k4*4+0][rr] = v.x; AsT[k4*4+1][rr] = v.y;
                AsT[k4*4+2][rr] = v.z; AsT[k4*4+3][rr] = v.w;
            }
        }
        {
            int c4 = t & 15;
            int kr = t >> 4;
#pragma unroll
            for (int kk = kr; kk < 32; kk += 16) {
                float4 w = *(const float4*)(W + (size_t)(k0+kk)*DIMM + c0 + c4*4);
                *(float4*)&Bs[kk][c4*4] = w;
            }
        }
        __syncthreads();
#pragma unroll
        for (int kk = 0; kk < 32; kk++) {
            float4 a4 = *(float4*)&AsT[kk][ty*4];
            ulonglong2 bb = *(const ulonglong2*)&Bs[kk][tx*4];
            u64p ar[4] = {fbcast(a4.x), fbcast(a4.y), fbcast(a4.z), fbcast(a4.w)};
#pragma unroll
            for (int i = 0; i < 4; i++) {
                ffma2(acc2[i][0], ar[i], bb.x);
                ffma2(acc2[i][1], ar[i], bb.y);
            }
        }
        __syncthreads();
    }

#pragma unroll
    for (int i = 0; i < 4; i++) {
        int gr = r0 + ty*4 + i;
        float2 p0 = funpack(acc2[i][0]);
        float2 p1 = funpack(acc2[i][1]);
        int c = c0 + tx*4;
        out[(size_t)gr*DIMM + c + 0] = p0.x + bias[c+0];
        out[(size_t)gr*DIMM + c + 1] = p0.y + bias[c+1];
        out[(size_t)gr*DIMM + c + 2] = p1.x + bias[c+2];
        out[(size_t)gr*DIMM + c + 3] = p1.y + bias[c+3];
    }
}

// =====================================================================
extern "C" void kernel_launch(void* const* d_in, const int* in_sizes, int n_in,
                              void* d_out, int out_size)
{
    const float* x      = (const float*)d_in[0];
    const float* memory = (const float*)d_in[1];
    const float* Wqkv   = (const float*)d_in[2];
    const float* Wrel   = (const float*)d_in[3];
    const float* Wout   = (const float*)d_in[4];
    const float* bout   = (const float*)d_in[5];
    const float* u_emb  = (const float*)d_in[6];
    const float* v_emb  = (const float*)d_in[7];
    float* out = (float*)d_out;

    (void)in_sizes; (void)n_in; (void)out_size;

    cudaFuncSetAttribute(attn_kernel, cudaFuncAttributeMaxDynamicSharedMemorySize,
                         ATTN_SMEM_FLOATS * (int)sizeof(float));

    qkv_kernel<<<dim3(1536/128, 8192/128), 256>>>(x, memory, Wqkv, u_emb, v_emb);
    krel_kernel<<<CTXL, 512>>>(Wrel);
    bd_kernel<<<dim3(CTXL/64, SEQL/64, BB*NH), 256>>>();
    attn_kernel<<<dim3(SEQL/32, BB*NH), 256, ATTN_SMEM_FLOATS * (int)sizeof(float)>>>();
    out_kernel<<<dim3(DIMM/64, 2048/64), 256>>>(Wout, bout, out);
}

// round 4
// speedup vs baseline: 1.1778x; 1.1778x over previous
#include <cuda_runtime.h>
#include <math.h>

#define BB 8
#define SEQL 256
#define MEML 768
#define TOT 1024
#define DIMM 512
#define NH 8
#define DH 64
#define INNERD 512
#define CTXL 1024
#define NOCTL 11

// ---------------- scratch (device globals; no allocation allowed) ----------------
__device__ float g_QU[BB*NH*SEQL*DH];            // q + u_emb   (4 MB)
__device__ float g_QV[BB*NH*SEQL*DH];            // q + v_emb   (4 MB)
__device__ float g_K [(size_t)BB*NH*TOT*DH];     // 16 MB
__device__ float g_V [(size_t)BB*NH*TOT*DH];     // 16 MB
__device__ float g_KrelT[NH*DH*CTXL];            // (R @ W_rel) TRANSPOSED [h][d][s] (2 MB)
__device__ float g_BD[(size_t)BB*NH*SEQL*CTXL];  // qv . Krel^T  (64 MB)
__device__ float g_AO[BB*SEQL*INNERD];           // attention output (4 MB)

// ---------------- tf32 mma helpers (3xTF32 split for fp32 accuracy) ----------------
__device__ __forceinline__ unsigned cvt_tf32(float x) {
    unsigned r; asm("cvt.rna.tf32.f32 %0, %1;" : "=r"(r) : "f"(x)); return r;
}
__device__ __forceinline__ void split_tf32(float x, unsigned& hi, unsigned& lo) {
    hi = cvt_tf32(x);
    lo = cvt_tf32(x - __uint_as_float(hi));
}
__device__ __forceinline__ void mma_tf32(float* acc, const unsigned* a, const unsigned* b) {
    asm volatile(
        "mma.sync.aligned.m16n8k8.row.col.f32.tf32.tf32.f32 "
        "{%0,%1,%2,%3}, {%4,%5,%6,%7}, {%8,%9}, {%0,%1,%2,%3};\n"
        : "+f"(acc[0]), "+f"(acc[1]), "+f"(acc[2]), "+f"(acc[3])
        : "r"(a[0]), "r"(a[1]), "r"(a[2]), "r"(a[3]), "r"(b[0]), "r"(b[1]));
}

// Common mainloop body macro: consumes As[128][36], Bs[32][136] -> acc[2][8][4].
// 8 warps: wm = (wid&3)*32, wn = (wid>>2)*64. Split-tf32, 3 mma per product.
#define MMA_MAINLOOP_STEP()                                                     \
    _Pragma("unroll")                                                           \
    for (int ks = 0; ks < 4; ks++) {                                            \
        unsigned Ah[2][4], Al[2][4];                                            \
        _Pragma("unroll")                                                       \
        for (int f = 0; f < 2; f++) {                                           \
            int r = wm + f*16 + (lane>>2);                                      \
            int c = ks*8 + (lane&3);                                            \
            split_tf32(As[r  ][c  ], Ah[f][0], Al[f][0]);                       \
            split_tf32(As[r+8][c  ], Ah[f][1], Al[f][1]);                       \
            split_tf32(As[r  ][c+4], Ah[f][2], Al[f][2]);                       \
            split_tf32(As[r+8][c+4], Ah[f][3], Al[f][3]);                       \
        }                                                                       \
        _Pragma("unroll")                                                       \
        for (int half = 0; half < 2; half++) {                                  \
            unsigned Bh[4][2], Bl[4][2];                                        \
            _Pragma("unroll")                                                   \
            for (int j = 0; j < 4; j++) {                                       \
                int n = wn + (half*4 + j)*8 + (lane>>2);                        \
                int k = ks*8 + (lane&3);                                        \
                split_tf32(Bs[k  ][n], Bh[j][0], Bl[j][0]);                     \
                split_tf32(Bs[k+4][n], Bh[j][1], Bl[j][1]);                     \
            }                                                                   \
            _Pragma("unroll")                                                   \
            for (int f = 0; f < 2; f++)                                         \
            _Pragma("unroll")                                                   \
            for (int j = 0; j < 4; j++) {                                       \
                float* a = acc[f][half*4 + j];                                  \
                mma_tf32(a, Ah[f], Bh[j]);                                      \
                mma_tf32(a, Ah[f], Bl[j]);                                      \
                mma_tf32(a, Al[f], Bh[j]);                                      \
            }                                                                   \
        }                                                                       \
    }

// =====================================================================
// Kernel 1: QKV projection via tensor cores.
// C[8192 x 1536] = concat(memory,x)[8192 x 512] @ W_qkv
// =====================================================================
__global__ __launch_bounds__(256) void qkv_kernel(
    const float* __restrict__ x, const float* __restrict__ mm,
    const float* __restrict__ W, const float* __restrict__ u_emb,
    const float* __restrict__ v_emb)
{
    __shared__ __align__(16) float As[128][36];
    __shared__ __align__(16) float Bs[32][136];
    int t = threadIdx.x;
    int lane = t & 31, wid = t >> 5;
    int wm = (wid & 3) * 32;
    int wn = (wid >> 2) * 64;
    int r0 = blockIdx.y * 128;
    int c0 = blockIdx.x * 128;

    float acc[2][8][4];
#pragma unroll
    for (int f = 0; f < 2; f++)
#pragma unroll
        for (int nf = 0; nf < 8; nf++)
#pragma unroll
            for (int e = 0; e < 4; e++) acc[f][nf][e] = 0.f;

    for (int k0 = 0; k0 < DIMM; k0 += 32) {
        __syncthreads();
#pragma unroll
        for (int q = 0; q < 4; q++) {
            int fid = t + q*256;
            int row = fid >> 3, c4 = fid & 7;
            int gr = r0 + row;
            int b = gr >> 10, pos = gr & 1023;
            const float* src = (pos < MEML)
                ? (mm + ((size_t)(b*MEML + pos))*DIMM)
                : (x  + ((size_t)(b*SEQL + pos - MEML))*DIMM);
            *(float4*)&As[row][c4*4] = *(const float4*)(src + k0 + c4*4);
        }
#pragma unroll
        for (int q = 0; q < 4; q++) {
            int fid = t + q*256;
            int row = fid >> 5, c4 = fid & 31;
            *(float4*)&Bs[row][c4*4] =
                *(const float4*)(W + (size_t)(k0+row)*1536 + c0 + c4*4);
        }
        __syncthreads();
        MMA_MAINLOOP_STEP()
    }

    // scatter epilogue
#pragma unroll
    for (int f = 0; f < 2; f++)
#pragma unroll
        for (int nf = 0; nf < 8; nf++)
#pragma unroll
            for (int e = 0; e < 4; e++) {
                int m = wm + f*16 + (lane>>2) + ((e>>1)<<3);
                int c = wn + nf*8 + ((lane&3)<<1) + (e&1);
                int gr = r0 + m;
                int gc = c0 + c;
                int b = gr >> 10, pos = gr & 1023;
                int which = gc >> 9;       // 0=q, 1=k, 2=v
                int cc = gc & 511;
                int h = cc >> 6, d = cc & 63;
                float val = acc[f][nf][e];
                if (which == 1) {
                    g_K[(((size_t)(b*NH + h))*TOT + pos)*DH + d] = val;
                } else if (which == 2) {
                    g_V[(((size_t)(b*NH + h))*TOT + pos)*DH + d] = val;
                } else if (pos >= MEML) {
                    int n = pos - MEML;
                    size_t idx = (((size_t)(b*NH + h))*SEQL + n)*DH + d;
                    g_QU[idx] = val + u_emb[d];
                    g_QV[idx] = val + v_emb[d];
                }
            }
}

// =====================================================================
// Kernel 2: KrelT[h][d][s] = (posenc(s) @ W_rel) transposed
// =====================================================================
__global__ __launch_bounds__(512) void krel_kernel(const float* __restrict__ Wrel)
{
    __shared__ float R[2*NOCTL];
    int s = blockIdx.x;
    int t = threadIdx.x;
    if (t < NOCTL) {
        float mult = exp2f((float)(t - (NOCTL-1))) * 3.14159265358979323846f;
        float arg = (float)s * mult;
        R[t]         = sinf(arg);
        R[t + NOCTL] = cosf(arg);
    }
    __syncthreads();
    float acc = 0.f;
#pragma unroll
    for (int j = 0; j < 2*NOCTL; j++) acc += R[j] * Wrel[j*INNERD + t];
    g_KrelT[(size_t)t*CTXL + s] = acc;   // t = h*64+d
}

// =====================================================================
// Kernel 3: BD[b,h,n,s] = QV[b,h,n,:] . Krel[h,s,:]  via tensor cores.
// Per bh: [256 x 1024] = QV[256 x 64] @ KrelT[64 x 1024]
// =====================================================================
__global__ __launch_bounds__(256) void bd_kernel()
{
    __shared__ __align__(16) float As[128][36];
    __shared__ __align__(16) float Bs[32][136];
    int t = threadIdx.x;
    int lane = t & 31, wid = t >> 5;
    int wm = (wid & 3) * 32;
    int wn = (wid >> 2) * 64;
    int bh = blockIdx.z;
    int h  = bh & 7;
    int n0 = blockIdx.y * 128;
    int s0 = blockIdx.x * 128;

    if (s0 > MEML + n0 + 127) return;   // never read by shifted access

    float acc[2][8][4];
#pragma unroll
    for (int f = 0; f < 2; f++)
#pragma unroll
        for (int nf = 0; nf < 8; nf++)
#pragma unroll
            for (int e = 0; e < 4; e++) acc[f][nf][e] = 0.f;

    const float* Ag = g_QV + ((size_t)bh*SEQL + n0)*DH;
    const float* Bg = g_KrelT + (size_t)h*DH*CTXL + s0;

    for (int k0 = 0; k0 < DH; k0 += 32) {
        __syncthreads();
#pragma unroll
        for (int q = 0; q < 4; q++) {
            int fid = t + q*256;
            int row = fid >> 3, c4 = fid & 7;
            *(float4*)&As[row][c4*4] = *(const float4*)(Ag + (size_t)row*DH + k0 + c4*4);
        }
#pragma unroll
        for (int q = 0; q < 4; q++) {
            int fid = t + q*256;
            int row = fid >> 5, c4 = fid & 31;
            *(float4*)&Bs[row][c4*4] = *(const float4*)(Bg + (size_t)(k0+row)*CTXL + c4*4);
        }
        __syncthreads();
        MMA_MAINLOOP_STEP()
    }

    float* out = g_BD + ((size_t)bh*SEQL + n0)*CTXL + s0;
#pragma unroll
    for (int f = 0; f < 2; f++)
#pragma unroll
        for (int nf = 0; nf < 8; nf++) {
            int m = wm + f*16 + (lane>>2);
            int c = wn + nf*8 + ((lane&3)<<1);
            *(float2*)&out[(size_t)m*CTXL + c]     = make_float2(acc[f][nf][0], acc[f][nf][1]);
            *(float2*)&out[(size_t)(m+8)*CTXL + c] = make_float2(acc[f][nf][2], acc[f][nf][3]);
        }
}

// =====================================================================
// Kernel 4: flash attention (round-2 version: 64-query tiles, scalar fp32)
// =====================================================================
#define ATTN_SMEM_FLOATS (4*64*68)

__global__ __launch_bounds__(256) void attn_kernel()
{
    extern __shared__ float smem[];
    float* QT = smem;            // [d][n] stride 68
    float* KT = QT + 64*68;      // [d][m]
    float* VT = KT + 64*68;      // [m][d]
    float* PT = VT + 64*68;      // [n][m]

    int t  = threadIdx.x;
    int tx = t & 15, ty = t >> 4;
    int bh = blockIdx.y;
    int b  = bh >> 3, h = bh & 7;
    int n0 = blockIdx.x * 64;

    {   // load QU tile (64 x 64), transposed
        int d4 = t & 15, row = t >> 4;
        const float* Q = g_QU + ((size_t)bh*SEQL + n0)*DH;
#pragma unroll
        for (int rr = row; rr < 64; rr += 16) {
            float4 a = *(const float4*)(Q + (size_t)rr*DH + d4*4);
            QT[(d4*4+0)*68 + rr] = a.x; QT[(d4*4+1)*68 + rr] = a.y;
            QT[(d4*4+2)*68 + rr] = a.z; QT[(d4*4+3)*68 + rr] = a.w;
        }
    }

    float O[4][4];
    float M[4], L[4];
    const float* bdp[4];
    int limit[4];
#pragma unroll
    for (int i = 0; i < 4; i++) {
        M[i] = -1e30f; L[i] = 0.f;
        int ng = n0 + ty*4 + i;
        limit[i] = MEML + ng;
        bdp[i] = g_BD + ((size_t)bh*SEQL + ng)*CTXL + limit[i];
#pragma unroll
        for (int j = 0; j < 4; j++) O[i][j] = 0.f;
    }

    int ntiles = (MEML + n0 + 63)/64 + 1;

    for (int tile = 0; tile < ntiles; tile++) {
        int m0 = tile * 64;
        __syncthreads();
        {
            int d4 = t & 15, row = t >> 4;
            const float* Kp = g_K + ((size_t)bh*TOT + m0)*DH;
            const float* Vp = g_V + ((size_t)bh*TOT + m0)*DH;
#pragma unroll
            for (int rr = row; rr < 64; rr += 16) {
                float4 a = *(const float4*)(Kp + (size_t)rr*DH + d4*4);
                KT[(d4*4+0)*68 + rr] = a.x; KT[(d4*4+1)*68 + rr] = a.y;
                KT[(d4*4+2)*68 + rr] = a.z; KT[(d4*4+3)*68 + rr] = a.w;
                *(float4*)&VT[rr*68 + d4*4] = *(const float4*)(Vp + (size_t)rr*DH + d4*4);
            }
        }
        __syncthreads();

        float S[4][4];
#pragma unroll
        for (int i = 0; i < 4; i++)
#pragma unroll
            for (int j = 0; j < 4; j++) S[i][j] = 0.f;
#pragma unroll 16
        for (int d = 0; d < 64; d++) {
            float4 a4 = *(float4*)&QT[d*68 + ty*4];
            float4 b4 = *(float4*)&KT[d*68 + tx*4];
            S[0][0] += a4.x*b4.x; S[0][1] += a4.x*b4.y; S[0][2] += a4.x*b4.z; S[0][3] += a4.x*b4.w;
            S[1][0] += a4.y*b4.x; S[1][1] += a4.y*b4.y; S[1][2] += a4.y*b4.z; S[1][3] += a4.y*b4.w;
            S[2][0] += a4.z*b4.x; S[2][1] += a4.z*b4.y; S[2][2] += a4.z*b4.z; S[2][3] += a4.z*b4.w;
            S[3][0] += a4.w*b4.x; S[3][1] += a4.w*b4.y; S[3][2] += a4.w*b4.z; S[3][3] += a4.w*b4.w;
        }

#pragma unroll
        for (int i = 0; i < 4; i++) {
            float mx = -1e30f;
#pragma unroll
            for (int j = 0; j < 4; j++) {
                int m = m0 + tx*4 + j;
                S[i][j] = (m <= limit[i]) ? (S[i][j] + bdp[i][-m]) * 0.125f : -1e30f;
                mx = fmaxf(mx, S[i][j]);
            }
#pragma unroll
            for (int off = 8; off; off >>= 1)
                mx = fmaxf(mx, __shfl_xor_sync(0xffffffffu, mx, off));
            float Mn = fmaxf(M[i], mx);
            float alpha = __expf(M[i] - Mn);
            M[i] = Mn;
            float s = 0.f;
#pragma unroll
            for (int j = 0; j < 4; j++) {
                float p = __expf(S[i][j] - Mn);
                S[i][j] = p;
                s += p;
            }
#pragma unroll
            for (int off = 8; off; off >>= 1)
                s += __shfl_xor_sync(0xffffffffu, s, off);
            L[i] = L[i]*alpha + s;
#pragma unroll
            for (int j = 0; j < 4; j++) O[i][j] *= alpha;
            *(float4*)&PT[(ty*4+i)*68 + tx*4] = make_float4(S[i][0], S[i][1], S[i][2], S[i][3]);
        }
        __syncthreads();

#pragma unroll 8
        for (int mmm = 0; mmm < 64; mmm++) {
            float p0 = PT[(ty*4+0)*68 + mmm];
            float p1 = PT[(ty*4+1)*68 + mmm];
            float p2 = PT[(ty*4+2)*68 + mmm];
            float p3 = PT[(ty*4+3)*68 + mmm];
            float4 v4 = *(float4*)&VT[mmm*68 + tx*4];
            O[0][0] += p0*v4.x; O[0][1] += p0*v4.y; O[0][2] += p0*v4.z; O[0][3] += p0*v4.w;
            O[1][0] += p1*v4.x; O[1][1] += p1*v4.y; O[1][2] += p1*v4.z; O[1][3] += p1*v4.w;
            O[2][0] += p2*v4.x; O[2][1] += p2*v4.y; O[2][2] += p2*v4.z; O[2][3] += p2*v4.w;
            O[3][0] += p3*v4.x; O[3][1] += p3*v4.y; O[3][2] += p3*v4.z; O[3][3] += p3*v4.w;
        }
    }

#pragma unroll
    for (int i = 0; i < 4; i++) {
        int ng = n0 + ty*4 + i;
        float r = 1.f / L[i];
        float4 o = make_float4(O[i][0]*r, O[i][1]*r, O[i][2]*r, O[i][3]*r);
        *(float4*)&g_AO[((size_t)(b*SEQL + ng))*INNERD + h*DH + tx*4] = o;
    }
}

// =====================================================================
// Kernel 5: out = AO[2048 x 512] @ W_out[512 x 512] + b_out  (tensor cores)
// =====================================================================
__global__ __launch_bounds__(256) void out_kernel(
    const float* __restrict__ W, const float* __restrict__ bias,
    float* __restrict__ out)
{
    __shared__ __align__(16) float As[128][36];
    __shared__ __align__(16) float Bs[32][136];
    int t = threadIdx.x;
    int lane = t & 31, wid = t >> 5;
    int wm = (wid & 3) * 32;
    int wn = (wid >> 2) * 64;
    int r0 = blockIdx.y * 128;
    int c0 = blockIdx.x * 128;

    float acc[2][8][4];
#pragma unroll
    for (int f = 0; f < 2; f++)
#pragma unroll
        for (int nf = 0; nf < 8; nf++)
#pragma unroll
            for (int e = 0; e < 4; e++) acc[f][nf][e] = 0.f;

    for (int k0 = 0; k0 < INNERD; k0 += 32) {
        __syncthreads();
#pragma unroll
        for (int q = 0; q < 4; q++) {
            int fid = t + q*256;
            int row = fid >> 3, c4 = fid & 7;
            *(float4*)&As[row][c4*4] =
                *(const float4*)(g_AO + (size_t)(r0+row)*INNERD + k0 + c4*4);
        }
#pragma unroll
        for (int q = 0; q < 4; q++) {
            int fid = t + q*256;
            int row = fid >> 5, c4 = fid & 31;
            *(float4*)&Bs[row][c4*4] =
                *(const float4*)(W + (size_t)(k0+row)*DIMM + c0 + c4*4);
        }
        __syncthreads();
        MMA_MAINLOOP_STEP()
    }

#pragma unroll
    for (int f = 0; f < 2; f++)
#pragma unroll
        for (int nf = 0; nf < 8; nf++) {
            int m = r0 + wm + f*16 + (lane>>2);
            int c = c0 + wn + nf*8 + ((lane&3)<<1);
            *(float2*)&out[(size_t)m*DIMM + c] =
                make_float2(acc[f][nf][0] + bias[c], acc[f][nf][1] + bias[c+1]);
            *(float2*)&out[(size_t)(m+8)*DIMM + c] =
                make_float2(acc[f][nf][2] + bias[c], acc[f][nf][3] + bias[c+1]);
        }
}

// =====================================================================
extern "C" void kernel_launch(void* const* d_in, const int* in_sizes, int n_in,
                              void* d_out, int out_size)
{
    const float* x      = (const float*)d_in[0];
    const float* memory = (const float*)d_in[1];
    const float* Wqkv   = (const float*)d_in[2];
    const float* Wrel   = (const float*)d_in[3];
    const float* Wout   = (const float*)d_in[4];
    const float* bout   = (const float*)d_in[5];
    const float* u_emb  = (const float*)d_in[6];
    const float* v_emb  = (const float*)d_in[7];
    float* out = (float*)d_out;

    (void)in_sizes; (void)n_in; (void)out_size;

    cudaFuncSetAttribute(attn_kernel, cudaFuncAttributeMaxDynamicSharedMemorySize,
                         ATTN_SMEM_FLOATS * (int)sizeof(float));

    qkv_kernel<<<dim3(1536/128, 8192/128), 256>>>(x, memory, Wqkv, u_emb, v_emb);
    krel_kernel<<<CTXL, 512>>>(Wrel);
    bd_kernel<<<dim3(CTXL/128, SEQL/128, BB*NH), 256>>>();
    attn_kernel<<<dim3(SEQL/64, BB*NH), 256, ATTN_SMEM_FLOATS * (int)sizeof(float)>>>();
    out_kernel<<<dim3(DIMM/128, 2048/128), 256>>>(Wout, bout, out);
}

// round 5
// speedup vs baseline: 1.9067x; 1.6188x over previous
#include <cuda_runtime.h>
#include <cuda_fp16.h>
#include <math.h>

#define BB 8
#define SEQL 256
#define MEML 768
#define TOT 1024
#define DIMM 512
#define NH 8
#define DH 64
#define INNERD 512
#define CTXL 1024
#define NOCTL 11

// ---------------- fp16 split helpers ----------------
__device__ __forceinline__ void split2h(float x, float y, __half2& h, __half2& l) {
    h = __floats2half2_rn(x, y);
    float2 f = __half22float2(h);
    l = __floats2half2_rn(x - f.x, y - f.y);
}
__device__ __forceinline__ void split1h(float x, __half& h, __half& l) {
    h = __float2half_rn(x);
    l = __float2half_rn(x - __half2float(h));
}
__device__ __forceinline__ void mma16816(float* c, const unsigned* a, const unsigned* b) {
    asm volatile(
        "mma.sync.aligned.m16n8k16.row.col.f32.f16.f16.f32 "
        "{%0,%1,%2,%3}, {%4,%5,%6,%7}, {%8,%9}, {%0,%1,%2,%3};\n"
        : "+f"(c[0]), "+f"(c[1]), "+f"(c[2]), "+f"(c[3])
        : "r"(a[0]), "r"(a[1]), "r"(a[2]), "r"(a[3]), "r"(b[0]), "r"(b[1]));
}

// ---------------- scratch (device globals) ----------------
__device__ __half g_Inh[8192*512],  g_Inl[8192*512];     // concat(memory,x) split
__device__ __half g_WqTh[1536*512], g_WqTl[1536*512];    // W_qkv^T split
__device__ __half g_WoTh[512*512],  g_WoTl[512*512];     // W_out^T split
__device__ __half g_QUh[BB*NH*SEQL*DH], g_QUl[BB*NH*SEQL*DH];
__device__ __half g_QVh[BB*NH*SEQL*DH], g_QVl[BB*NH*SEQL*DH];
__device__ __half g_Kh [BB*NH*TOT*DH],  g_Kl [BB*NH*TOT*DH];
__device__ __half g_VTh[BB*NH*DH*TOT],  g_VTl[BB*NH*DH*TOT];   // V transposed [bh][d][key]
__device__ __half g_Krelh[NH*CTXL*DH],  g_Krell[NH*CTXL*DH];   // [h][s][d]
__device__ __half g_AOh[BB*SEQL*INNERD], g_AOl[BB*SEQL*INNERD];
__device__ float  g_BD[BB*NH*SEQL*CTXL];                 // fp32 BD (64 MB)

// =====================================================================
// pre_in: split concat(memory, x) -> g_Inh/g_Inl  [8192][512]
// =====================================================================
__global__ __launch_bounds__(256) void pre_in_kernel(
    const float* __restrict__ x, const float* __restrict__ mm)
{
    int fid = blockIdx.x*256 + threadIdx.x;          // one float4 each
    int gr = fid >> 7;                               // row (8192)
    int c4 = fid & 127;                              // float4 within 512
    int b = gr >> 10, pos = gr & 1023;
    const float* src = (pos < MEML)
        ? (mm + ((size_t)(b*MEML + pos))*DIMM)
        : (x  + ((size_t)(b*SEQL + pos - MEML))*DIMM);
    float4 v = *(const float4*)(src + c4*4);
    size_t idx = (size_t)gr*512 + c4*4;
    __half2 h01, l01, h23, l23;
    split2h(v.x, v.y, h01, l01);
    split2h(v.z, v.w, h23, l23);
    *(__half2*)&g_Inh[idx]   = h01; *(__half2*)&g_Inl[idx]   = l01;
    *(__half2*)&g_Inh[idx+2] = h23; *(__half2*)&g_Inl[idx+2] = l23;
}

// =====================================================================
// pre_w: transpose + split W[512][N] -> WT_h/l [N][512]
// which = 0 -> W_qkv (N=1536), 1 -> W_out (N=512)
// =====================================================================
__global__ __launch_bounds__(256) void pre_w_kernel(
    const float* __restrict__ src, int N, int which)
{
    __shared__ float T[64][68];
    int t = threadIdx.x;
    int n0 = blockIdx.x * 64;
    int k0 = blockIdx.y * 64;
    __half* dh = which ? g_WoTh : g_WqTh;
    __half* dl = which ? g_WoTl : g_WqTl;
#pragma unroll
    for (int i = 0; i < 4; i++) {
        int fid = t + i*256;
        int kr = fid >> 4, c4 = fid & 15;
        *(float4*)&T[kr][c4*4] = *(const float4*)(src + (size_t)(k0+kr)*N + n0 + c4*4);
    }
    __syncthreads();
#pragma unroll
    for (int i = 0; i < 8; i++) {
        int idx = t + i*256;
        int n = idx >> 5, kk = (idx & 31)*2;
        __half2 h, l;
        split2h(T[kk][n], T[kk+1][n], h, l);
        size_t o = (size_t)(n0+n)*512 + k0 + kk;
        *(__half2*)&dh[o] = h; *(__half2*)&dl[o] = l;
    }
}

// =====================================================================
// GEMM core: one 64-k smem block, 8 warps, 128x128 tile, split-fp16 3x mma
// Ah/Al: [128][72] halves (row-major A tile), Bh/Bl: [128][72] (B^T tile [n][k])
// =====================================================================
__device__ __forceinline__ void gemm_block_k64(
    const __half* Ah, const __half* Al, const __half* Bh, const __half* Bl,
    int lane, int wm, int wn, float acc[2][8][4])
{
#pragma unroll
    for (int kb = 0; kb < 64; kb += 16) {
        unsigned ah[2][4], al[2][4];
        int cA = kb + 2*(lane & 3);
#pragma unroll
        for (int f = 0; f < 2; f++) {
            int r = wm + f*16 + (lane >> 2);
            ah[f][0] = *(const unsigned*)&Ah[r*72 + cA];
            ah[f][1] = *(const unsigned*)&Ah[(r+8)*72 + cA];
            ah[f][2] = *(const unsigned*)&Ah[r*72 + cA + 8];
            ah[f][3] = *(const unsigned*)&Ah[(r+8)*72 + cA + 8];
            al[f][0] = *(const unsigned*)&Al[r*72 + cA];
            al[f][1] = *(const unsigned*)&Al[(r+8)*72 + cA];
            al[f][2] = *(const unsigned*)&Al[r*72 + cA + 8];
            al[f][3] = *(const unsigned*)&Al[(r+8)*72 + cA + 8];
        }
#pragma unroll
        for (int j = 0; j < 8; j++) {
            int n = wn + j*8 + (lane >> 2);
            unsigned bh[2], bl[2];
            bh[0] = *(const unsigned*)&Bh[n*72 + cA];
            bh[1] = *(const unsigned*)&Bh[n*72 + cA + 8];
            bl[0] = *(const unsigned*)&Bl[n*72 + cA];
            bl[1] = *(const unsigned*)&Bl[n*72 + cA + 8];
#pragma unroll
            for (int f = 0; f < 2; f++) {
                mma16816(acc[f][j], ah[f], bh);
                mma16816(acc[f][j], ah[f], bl);
                mma16816(acc[f][j], al[f], bh);
            }
        }
    }
}

#define GEMM_SMEM_BYTES (4*128*72*2)

// =====================================================================
// Kernel: QKV projection. [8192x1536] = In[8192x512] @ Wqkv
// =====================================================================
__global__ __launch_bounds__(256) void qkv_kernel(
    const float* __restrict__ u_emb, const float* __restrict__ v_emb)
{
    extern __shared__ __half smh[];
    __half* Ah = smh;
    __half* Al = Ah + 128*72;
    __half* Bh = Al + 128*72;
    __half* Bl = Bh + 128*72;
    int t = threadIdx.x, lane = t & 31, wid = t >> 5;
    int wm = (wid & 3)*32, wn = (wid >> 2)*64;
    int r0 = blockIdx.y*128, c0 = blockIdx.x*128;

    float acc[2][8][4];
#pragma unroll
    for (int f = 0; f < 2; f++)
#pragma unroll
        for (int j = 0; j < 8; j++)
#pragma unroll
            for (int e = 0; e < 4; e++) acc[f][j][e] = 0.f;

    for (int k0 = 0; k0 < DIMM; k0 += 64) {
        __syncthreads();
#pragma unroll
        for (int i = 0; i < 4; i++) {
            int fid = t + i*256;
            int row = fid >> 3, c8 = fid & 7;
            *(uint4*)&Ah[row*72 + c8*8] = *(const uint4*)&g_Inh[(size_t)(r0+row)*512 + k0 + c8*8];
            *(uint4*)&Al[row*72 + c8*8] = *(const uint4*)&g_Inl[(size_t)(r0+row)*512 + k0 + c8*8];
            *(uint4*)&Bh[row*72 + c8*8] = *(const uint4*)&g_WqTh[(size_t)(c0+row)*512 + k0 + c8*8];
            *(uint4*)&Bl[row*72 + c8*8] = *(const uint4*)&g_WqTl[(size_t)(c0+row)*512 + k0 + c8*8];
        }
        __syncthreads();
        gemm_block_k64(Ah, Al, Bh, Bl, lane, wm, wn, acc);
    }

#pragma unroll
    for (int f = 0; f < 2; f++)
#pragma unroll
        for (int j = 0; j < 8; j++)
#pragma unroll
            for (int ii = 0; ii < 2; ii++) {
                int gr = r0 + wm + f*16 + (lane >> 2) + ii*8;
                int gc = c0 + wn + j*8 + 2*(lane & 3);
                float v0 = acc[f][j][2*ii], v1 = acc[f][j][2*ii+1];
                int b = gr >> 10, pos = gr & 1023;
                int which = gc >> 9, cc = gc & 511;
                int h = cc >> 6, d = cc & 63;
                int bh = b*NH + h;
                if (which == 1) {
                    __half2 hh, ll; split2h(v0, v1, hh, ll);
                    size_t idx = ((size_t)bh*TOT + pos)*DH + d;
                    *(__half2*)&g_Kh[idx] = hh; *(__half2*)&g_Kl[idx] = ll;
                } else if (which == 2) {
                    __half h0, l0, h1, l1;
                    split1h(v0, h0, l0); split1h(v1, h1, l1);
                    size_t i0 = ((size_t)bh*DH + d)*TOT + pos;
                    g_VTh[i0] = h0;      g_VTl[i0] = l0;
                    g_VTh[i0+TOT] = h1;  g_VTl[i0+TOT] = l1;
                } else if (pos >= MEML) {
                    int n = pos - MEML;
                    size_t idx = ((size_t)bh*SEQL + n)*DH + d;
                    __half2 hh, ll;
                    split2h(v0 + u_emb[d], v1 + u_emb[d+1], hh, ll);
                    *(__half2*)&g_QUh[idx] = hh; *(__half2*)&g_QUl[idx] = ll;
                    split2h(v0 + v_emb[d], v1 + v_emb[d+1], hh, ll);
                    *(__half2*)&g_QVh[idx] = hh; *(__half2*)&g_QVl[idx] = ll;
                }
            }
}

// =====================================================================
// krel: Krel[h][s][d] = posenc(s) @ W_rel, split fp16
// =====================================================================
__global__ __launch_bounds__(512) void krel_kernel(const float* __restrict__ Wrel)
{
    __shared__ float R[2*NOCTL];
    int s = blockIdx.x;
    int t = threadIdx.x;
    if (t < NOCTL) {
        float mult = exp2f((float)(t - (NOCTL-1))) * 3.14159265358979323846f;
        float arg = (float)s * mult;
        R[t]         = sinf(arg);
        R[t + NOCTL] = cosf(arg);
    }
    __syncthreads();
    float acc = 0.f;
#pragma unroll
    for (int j = 0; j < 2*NOCTL; j++) acc += R[j] * Wrel[j*INNERD + t];
    int h = t >> 6, d = t & 63;
    __half hh, ll; split1h(acc, hh, ll);
    size_t idx = ((size_t)h*CTXL + s)*DH + d;
    g_Krelh[idx] = hh; g_Krell[idx] = ll;
}

// =====================================================================
// bd: BD[bh][n][s] = QV[n][d] . Krel[s][d]  (k=64, single smem block)
// =====================================================================
__global__ __launch_bounds__(256) void bd_kernel()
{
    extern __shared__ __half smh[];
    __half* Ah = smh;
    __half* Al = Ah + 128*72;
    __half* Bh = Al + 128*72;
    __half* Bl = Bh + 128*72;
    int t = threadIdx.x, lane = t & 31, wid = t >> 5;
    int wm = (wid & 3)*32, wn = (wid >> 2)*64;
    int bh = blockIdx.z, h = bh & 7;
    int n0 = blockIdx.y*128, s0 = blockIdx.x*128;
    if (s0 > MEML + n0 + 127) return;

    float acc[2][8][4];
#pragma unroll
    for (int f = 0; f < 2; f++)
#pragma unroll
        for (int j = 0; j < 8; j++)
#pragma unroll
            for (int e = 0; e < 4; e++) acc[f][j][e] = 0.f;

#pragma unroll
    for (int i = 0; i < 4; i++) {
        int fid = t + i*256;
        int row = fid >> 3, c8 = fid & 7;
        *(uint4*)&Ah[row*72 + c8*8] = *(const uint4*)&g_QVh[((size_t)bh*SEQL + n0 + row)*DH + c8*8];
        *(uint4*)&Al[row*72 + c8*8] = *(const uint4*)&g_QVl[((size_t)bh*SEQL + n0 + row)*DH + c8*8];
        *(uint4*)&Bh[row*72 + c8*8] = *(const uint4*)&g_Krelh[((size_t)h*CTXL + s0 + row)*DH + c8*8];
        *(uint4*)&Bl[row*72 + c8*8] = *(const uint4*)&g_Krell[((size_t)h*CTXL + s0 + row)*DH + c8*8];
    }
    __syncthreads();
    gemm_block_k64(Ah, Al, Bh, Bl, lane, wm, wn, acc);

#pragma unroll
    for (int f = 0; f < 2; f++)
#pragma unroll
        for (int j = 0; j < 8; j++)
#pragma unroll
            for (int ii = 0; ii < 2; ii++) {
                int n = n0 + wm + f*16 + (lane >> 2) + ii*8;
                int s = s0 + wn + j*8 + 2*(lane & 3);
                *(float2*)&g_BD[((size_t)bh*SEQL + n)*CTXL + s] =
                    make_float2(acc[f][j][2*ii], acc[f][j][2*ii+1]);
            }
}

// =====================================================================
// attn: tensor-core flash attention. 128 threads, 64-query tile per CTA.
// warp = 16 queries x 64 keys. QK^T and P.V via split-fp16 mma.
// =====================================================================
#define ATTN_SMEM_BYTES (8*64*72*2)

__global__ __launch_bounds__(128) void attn_kernel()
{
    extern __shared__ __half smh[];
    __half* Qh = smh;              // [q][d]  64x72
    __half* Ql = Qh + 64*72;
    __half* Kh = Ql + 64*72;       // [key][d]
    __half* Kl = Kh + 64*72;
    __half* Vh = Kl + 64*72;       // VT: [d][key]
    __half* Vl = Vh + 64*72;
    __half* Ph = Vl + 64*72;       // [q][key]
    __half* Pl = Ph + 64*72;

    int t = threadIdx.x, lane = t & 31, wq = t >> 5;
    int bh = blockIdx.y, b = bh >> 3, h = bh & 7;
    int n0 = blockIdx.x * 64;

    // load Q tile (hi/lo)
#pragma unroll
    for (int i = 0; i < 4; i++) {
        int fid = t + i*128;
        int row = fid >> 3, c8 = fid & 7;
        *(uint4*)&Qh[row*72 + c8*8] = *(const uint4*)&g_QUh[((size_t)bh*SEQL + n0 + row)*DH + c8*8];
        *(uint4*)&Ql[row*72 + c8*8] = *(const uint4*)&g_QUl[((size_t)bh*SEQL + n0 + row)*DH + c8*8];
    }

    float O[8][4];
#pragma unroll
    for (int j = 0; j < 8; j++)
#pragma unroll
        for (int e = 0; e < 4; e++) O[j][e] = 0.f;
    float M[2] = {-1e30f, -1e30f}, L[2] = {0.f, 0.f};

    int rl0 = wq*16 + (lane >> 2);
    int c0j = 2*(lane & 3);
    const float* BD0 = g_BD + ((size_t)bh*SEQL + (n0 + rl0))*CTXL;
    const float* BD1 = BD0 + 8*CTXL;
    int lim0 = MEML + n0 + rl0, lim1 = lim0 + 8;

    int ntiles = (MEML + n0 + 63)/64 + 1;
    for (int tile = 0; tile < ntiles; tile++) {
        int m0 = tile*64;
        __syncthreads();
#pragma unroll
        for (int i = 0; i < 4; i++) {
            int fid = t + i*128;
            int row = fid >> 3, c8 = fid & 7;
            *(uint4*)&Kh[row*72 + c8*8] = *(const uint4*)&g_Kh[((size_t)bh*TOT + m0 + row)*DH + c8*8];
            *(uint4*)&Kl[row*72 + c8*8] = *(const uint4*)&g_Kl[((size_t)bh*TOT + m0 + row)*DH + c8*8];
            *(uint4*)&Vh[row*72 + c8*8] = *(const uint4*)&g_VTh[((size_t)bh*DH + row)*TOT + m0 + c8*8];
            *(uint4*)&Vl[row*72 + c8*8] = *(const uint4*)&g_VTl[((size_t)bh*DH + row)*TOT + m0 + c8*8];
        }
        __syncthreads();

        // ---- S = Q . K^T ----
        float S[8][4];
#pragma unroll
        for (int j = 0; j < 8; j++)
#pragma unroll
            for (int e = 0; e < 4; e++) S[j][e] = 0.f;
#pragma unroll
        for (int kb = 0; kb < 64; kb += 16) {
            int cA = kb + c0j;
            int r = wq*16 + (lane >> 2);
            unsigned ah[4], al[4];
            ah[0] = *(const unsigned*)&Qh[r*72 + cA];
            ah[1] = *(const unsigned*)&Qh[(r+8)*72 + cA];
            ah[2] = *(const unsigned*)&Qh[r*72 + cA + 8];
            ah[3] = *(const unsigned*)&Qh[(r+8)*72 + cA + 8];
            al[0] = *(const unsigned*)&Ql[r*72 + cA];
            al[1] = *(const unsigned*)&Ql[(r+8)*72 + cA];
            al[2] = *(const unsigned*)&Ql[r*72 + cA + 8];
            al[3] = *(const unsigned*)&Ql[(r+8)*72 + cA + 8];
#pragma unroll
            for (int j = 0; j < 8; j++) {
                int n = j*8 + (lane >> 2);
                unsigned bhf[2], blf[2];
                bhf[0] = *(const unsigned*)&Kh[n*72 + cA];
                bhf[1] = *(const unsigned*)&Kh[n*72 + cA + 8];
                blf[0] = *(const unsigned*)&Kl[n*72 + cA];
                blf[1] = *(const unsigned*)&Kl[n*72 + cA + 8];
                mma16816(S[j], ah, bhf);
                mma16816(S[j], ah, blf);
                mma16816(S[j], al, bhf);
            }
        }

        // ---- BD add + mask + online softmax; write P (hi/lo) ----
#pragma unroll
        for (int i = 0; i < 2; i++) {
            const float* BD = i ? BD1 : BD0;
            int lim = i ? lim1 : lim0;
            float mx = -1e30f;
#pragma unroll
            for (int j = 0; j < 8; j++) {
                int m = m0 + j*8 + c0j;
                float v0 = (m   <= lim) ? (S[j][2*i]   + BD[lim-m  ])*0.125f : -1e30f;
                float v1 = (m+1 <= lim) ? (S[j][2*i+1] + BD[lim-m-1])*0.125f : -1e30f;
                S[j][2*i] = v0; S[j][2*i+1] = v1;
                mx = fmaxf(mx, fmaxf(v0, v1));
            }
            mx = fmaxf(mx, __shfl_xor_sync(0xffffffffu, mx, 1));
            mx = fmaxf(mx, __shfl_xor_sync(0xffffffffu, mx, 2));
            float Mn = fmaxf(M[i], mx);
            float alpha = __expf(M[i] - Mn);
            M[i] = Mn;
            float sum = 0.f;
            int rl = rl0 + 8*i;
#pragma unroll
            for (int j = 0; j < 8; j++) {
                float p0 = __expf(S[j][2*i]   - Mn);
                float p1 = __expf(S[j][2*i+1] - Mn);
                sum += p0 + p1;
                __half2 hh, ll; split2h(p0, p1, hh, ll);
                *(__half2*)&Ph[rl*72 + j*8 + c0j] = hh;
                *(__half2*)&Pl[rl*72 + j*8 + c0j] = ll;
                O[j][2*i] *= alpha; O[j][2*i+1] *= alpha;
            }
            sum += __shfl_xor_sync(0xffffffffu, sum, 1);
            sum += __shfl_xor_sync(0xffffffffu, sum, 2);
            L[i] = L[i]*alpha + sum;
        }
        __syncwarp();

        // ---- O += P . V ----
#pragma unroll
        for (int kb = 0; kb < 64; kb += 16) {
            int cA = kb + c0j;
            int r = wq*16 + (lane >> 2);
            unsigned ah[4], al[4];
            ah[0] = *(const unsigned*)&Ph[r*72 + cA];
            ah[1] = *(const unsigned*)&Ph[(r+8)*72 + cA];
            ah[2] = *(const unsigned*)&Ph[r*72 + cA + 8];
            ah[3] = *(const unsigned*)&Ph[(r+8)*72 + cA + 8];
            al[0] = *(const unsigned*)&Pl[r*72 + cA];
            al[1] = *(const unsigned*)&Pl[(r+8)*72 + cA];
            al[2] = *(const unsigned*)&Pl[r*72 + cA + 8];
            al[3] = *(const unsigned*)&Pl[(r+8)*72 + cA + 8];
#pragma unroll
            for (int j = 0; j < 8; j++) {
                int n = j*8 + (lane >> 2);
                unsigned bhf[2], blf[2];
                bhf[0] = *(const unsigned*)&Vh[n*72 + cA];
                bhf[1] = *(const unsigned*)&Vh[n*72 + cA + 8];
                blf[0] = *(const unsigned*)&Vl[n*72 + cA];
                blf[1] = *(const unsigned*)&Vl[n*72 + cA + 8];
                mma16816(O[j], ah, bhf);
                mma16816(O[j], ah, blf);
                mma16816(O[j], al, bhf);
            }
        }
    }

    // epilogue: normalize, split, store AO (fp16 hi/lo)
#pragma unroll
    for (int i = 0; i < 2; i++) {
        float inv = 1.f / L[i];
        int row = b*SEQL + n0 + rl0 + 8*i;
#pragma unroll
        for (int j = 0; j < 8; j++) {
            float o0 = O[j][2*i]*inv, o1 = O[j][2*i+1]*inv;
            __half2 hh, ll; split2h(o0, o1, hh, ll);
            size_t idx = (size_t)row*INNERD + h*DH + j*8 + c0j;
            *(__half2*)&g_AOh[idx] = hh; *(__half2*)&g_AOl[idx] = ll;
        }
    }
}

// =====================================================================
// out: [2048x512] = AO[2048x512] @ W_out + b_out
// =====================================================================
__global__ __launch_bounds__(256) void out_kernel(
    const float* __restrict__ bias, float* __restrict__ out)
{
    extern __shared__ __half smh[];
    __half* Ah = smh;
    __half* Al = Ah + 128*72;
    __half* Bh = Al + 128*72;
    __half* Bl = Bh + 128*72;
    int t = threadIdx.x, lane = t & 31, wid = t >> 5;
    int wm = (wid & 3)*32, wn = (wid >> 2)*64;
    int r0 = blockIdx.y*128, c0 = blockIdx.x*128;

    float acc[2][8][4];
#pragma unroll
    for (int f = 0; f < 2; f++)
#pragma unroll
        for (int j = 0; j < 8; j++)
#pragma unroll
            for (int e = 0; e < 4; e++) acc[f][j][e] = 0.f;

    for (int k0 = 0; k0 < INNERD; k0 += 64) {
        __syncthreads();
#pragma unroll
        for (int i = 0; i < 4; i++) {
            int fid = t + i*256;
            int row = fid >> 3, c8 = fid & 7;
            *(uint4*)&Ah[row*72 + c8*8] = *(const uint4*)&g_AOh[(size_t)(r0+row)*512 + k0 + c8*8];
            *(uint4*)&Al[row*72 + c8*8] = *(const uint4*)&g_AOl[(size_t)(r0+row)*512 + k0 + c8*8];
            *(uint4*)&Bh[row*72 + c8*8] = *(const uint4*)&g_WoTh[(size_t)(c0+row)*512 + k0 + c8*8];
            *(uint4*)&Bl[row*72 + c8*8] = *(const uint4*)&g_WoTl[(size_t)(c0+row)*512 + k0 + c8*8];
        }
        __syncthreads();
        gemm_block_k64(Ah, Al, Bh, Bl, lane, wm, wn, acc);
    }

#pragma unroll
    for (int f = 0; f < 2; f++)
#pragma unroll
        for (int j = 0; j < 8; j++)
#pragma unroll
            for (int ii = 0; ii < 2; ii++) {
                int gr = r0 + wm + f*16 + (lane >> 2) + ii*8;
                int gc = c0 + wn + j*8 + 2*(lane & 3);
                *(float2*)&out[(size_t)gr*DIMM + gc] =
                    make_float2(acc[f][j][2*ii] + bias[gc], acc[f][j][2*ii+1] + bias[gc+1]);
            }
}

// =====================================================================
extern "C" void kernel_launch(void* const* d_in, const int* in_sizes, int n_in,
                              void* d_out, int out_size)
{
    const float* x      = (const float*)d_in[0];
    const float* memory = (const float*)d_in[1];
    const float* Wqkv   = (const float*)d_in[2];
    const float* Wrel   = (const float*)d_in[3];
    const float* Wout   = (const float*)d_in[4];
    const float* bout   = (const float*)d_in[5];
    const float* u_emb  = (const float*)d_in[6];
    const float* v_emb  = (const float*)d_in[7];
    float* out = (float*)d_out;
    (void)in_sizes; (void)n_in; (void)out_size;

    static int configured = 0;
    cudaFuncSetAttribute(qkv_kernel,  cudaFuncAttributeMaxDynamicSharedMemorySize, GEMM_SMEM_BYTES);
    cudaFuncSetAttribute(bd_kernel,   cudaFuncAttributeMaxDynamicSharedMemorySize, GEMM_SMEM_BYTES);
    cudaFuncSetAttribute(out_kernel,  cudaFuncAttributeMaxDynamicSharedMemorySize, GEMM_SMEM_BYTES);
    cudaFuncSetAttribute(attn_kernel, cudaFuncAttributeMaxDynamicSharedMemorySize, ATTN_SMEM_BYTES);
    (void)configured;

    pre_in_kernel<<<8192*512/4/256, 256>>>(x, memory);
    pre_w_kernel<<<dim3(1536/64, 512/64), 256>>>(Wqkv, 1536, 0);
    pre_w_kernel<<<dim3(512/64, 512/64), 256>>>(Wout, 512, 1);
    krel_kernel<<<CTXL, 512>>>(Wrel);
    qkv_kernel<<<dim3(1536/128, 8192/128), 256, GEMM_SMEM_BYTES>>>(u_emb, v_emb);
    bd_kernel<<<dim3(CTXL/128, SEQL/128, BB*NH), 256, GEMM_SMEM_BYTES>>>();
    attn_kernel<<<dim3(SEQL/64, BB*NH), 128, ATTN_SMEM_BYTES>>>();
    out_kernel<<<dim3(DIMM/128, 2048/128), 256, GEMM_SMEM_BYTES>>>(bout, out);
}

// round 6
// speedup vs baseline: 2.7331x; 1.4334x over previous
#include <cuda_runtime.h>
#include <cuda_fp16.h>
#include <math.h>

#define BB 8
#define SEQL 256
#define MEML 768
#define TOT 1024
#define DIMM 512
#define NH 8
#define DH 64
#define INNERD 512
#define CTXL 1024
#define NOCTL 11

// ---------------- fp16 split helpers ----------------
__device__ __forceinline__ void split2h(float x, float y, __half2& h, __half2& l) {
    h = __floats2half2_rn(x, y);
    float2 f = __half22float2(h);
    l = __floats2half2_rn(x - f.x, y - f.y);
}
__device__ __forceinline__ void split1h(float x, __half& h, __half& l) {
    h = __float2half_rn(x);
    l = __float2half_rn(x - __half2float(h));
}
__device__ __forceinline__ void mma16816(float* c, const unsigned* a, const unsigned* b) {
    asm volatile(
        "mma.sync.aligned.m16n8k16.row.col.f32.f16.f16.f32 "
        "{%0,%1,%2,%3}, {%4,%5,%6,%7}, {%8,%9}, {%0,%1,%2,%3};\n"
        : "+f"(c[0]), "+f"(c[1]), "+f"(c[2]), "+f"(c[3])
        : "r"(a[0]), "r"(a[1]), "r"(a[2]), "r"(a[3]), "r"(b[0]), "r"(b[1]));
}
// ---------------- cp.async helpers ----------------
__device__ __forceinline__ void cp16(void* dst, const void* src) {
    unsigned d = (unsigned)__cvta_generic_to_shared(dst);
    asm volatile("cp.async.cg.shared.global [%0], [%1], 16;" :: "r"(d), "l"(src));
}
__device__ __forceinline__ void cp_commit() {
    asm volatile("cp.async.commit_group;");
}
template<int N> __device__ __forceinline__ void cp_wait() {
    asm volatile("cp.async.wait_group %0;" :: "n"(N));
}

// ---------------- scratch (device globals) ----------------
__device__ __half g_Inh[8192*512],  g_Inl[8192*512];     // concat(memory,x) split
__device__ __half g_WqTh[1536*512], g_WqTl[1536*512];    // W_qkv^T split
__device__ __half g_WoTh[512*512],  g_WoTl[512*512];     // W_out^T split
__device__ __half g_QUh[BB*NH*SEQL*DH], g_QUl[BB*NH*SEQL*DH];
__device__ __half g_QVh[BB*NH*SEQL*DH], g_QVl[BB*NH*SEQL*DH];
__device__ __half g_Kh [BB*NH*TOT*DH],  g_Kl [BB*NH*TOT*DH];
__device__ __half g_VTh[BB*NH*DH*TOT],  g_VTl[BB*NH*DH*TOT];   // V transposed [bh][d][key]
__device__ __half g_Krelh[NH*CTXL*DH],  g_Krell[NH*CTXL*DH];   // [h][s][d]
__device__ __half g_AOh[BB*SEQL*INNERD], g_AOl[BB*SEQL*INNERD];
__device__ float  g_BDs[BB*NH*SEQL*TOT];   // BD pre-shifted: [bh][n][m] = BD at s=MEML+n-m

// =====================================================================
// pre_in: split concat(memory, x) -> g_Inh/g_Inl  [8192][512]
// =====================================================================
__global__ __launch_bounds__(256) void pre_in_kernel(
    const float* __restrict__ x, const float* __restrict__ mm)
{
    int fid = blockIdx.x*256 + threadIdx.x;
    int gr = fid >> 7;
    int c4 = fid & 127;
    int b = gr >> 10, pos = gr & 1023;
    const float* src = (pos < MEML)
        ? (mm + ((size_t)(b*MEML + pos))*DIMM)
        : (x  + ((size_t)(b*SEQL + pos - MEML))*DIMM);
    float4 v = *(const float4*)(src + c4*4);
    size_t idx = (size_t)gr*512 + c4*4;
    __half2 h01, l01, h23, l23;
    split2h(v.x, v.y, h01, l01);
    split2h(v.z, v.w, h23, l23);
    *(__half2*)&g_Inh[idx]   = h01; *(__half2*)&g_Inl[idx]   = l01;
    *(__half2*)&g_Inh[idx+2] = h23; *(__half2*)&g_Inl[idx+2] = l23;
}

// =====================================================================
// pre_w: transpose + split W[512][N] -> WT_h/l [N][512]
// =====================================================================
__global__ __launch_bounds__(256) void pre_w_kernel(
    const float* __restrict__ src, int N, int which)
{
    __shared__ float T[64][68];
    int t = threadIdx.x;
    int n0 = blockIdx.x * 64;
    int k0 = blockIdx.y * 64;
    __half* dh = which ? g_WoTh : g_WqTh;
    __half* dl = which ? g_WoTl : g_WqTl;
#pragma unroll
    for (int i = 0; i < 4; i++) {
        int fid = t + i*256;
        int kr = fid >> 4, c4 = fid & 15;
        *(float4*)&T[kr][c4*4] = *(const float4*)(src + (size_t)(k0+kr)*N + n0 + c4*4);
    }
    __syncthreads();
#pragma unroll
    for (int i = 0; i < 8; i++) {
        int idx = t + i*256;
        int n = idx >> 5, kk = (idx & 31)*2;
        __half2 h, l;
        split2h(T[kk][n], T[kk+1][n], h, l);
        size_t o = (size_t)(n0+n)*512 + k0 + kk;
        *(__half2*)&dh[o] = h; *(__half2*)&dl[o] = l;
    }
}

// =====================================================================
// GEMM core (one k=64 block): As/Bs strides 72 halves, split-fp16, 3x mma
// =====================================================================
__device__ __forceinline__ void gemm_block_k64(
    const __half* Ah, const __half* Al, const __half* Bh, const __half* Bl,
    int lane, int wm, int wn, float acc[2][8][4])
{
#pragma unroll
    for (int kb = 0; kb < 64; kb += 16) {
        unsigned ah[2][4], al[2][4];
        int cA = kb + 2*(lane & 3);
#pragma unroll
        for (int f = 0; f < 2; f++) {
            int r = wm + f*16 + (lane >> 2);
            ah[f][0] = *(const unsigned*)&Ah[r*72 + cA];
            ah[f][1] = *(const unsigned*)&Ah[(r+8)*72 + cA];
            ah[f][2] = *(const unsigned*)&Ah[r*72 + cA + 8];
            ah[f][3] = *(const unsigned*)&Ah[(r+8)*72 + cA + 8];
            al[f][0] = *(const unsigned*)&Al[r*72 + cA];
            al[f][1] = *(const unsigned*)&Al[(r+8)*72 + cA];
            al[f][2] = *(const unsigned*)&Al[r*72 + cA + 8];
            al[f][3] = *(const unsigned*)&Al[(r+8)*72 + cA + 8];
        }
#pragma unroll
        for (int j = 0; j < 8; j++) {
            int n = wn + j*8 + (lane >> 2);
            unsigned bh[2], bl[2];
            bh[0] = *(const unsigned*)&Bh[n*72 + cA];
            bh[1] = *(const unsigned*)&Bh[n*72 + cA + 8];
            bl[0] = *(const unsigned*)&Bl[n*72 + cA];
            bl[1] = *(const unsigned*)&Bl[n*72 + cA + 8];
#pragma unroll
            for (int f = 0; f < 2; f++) {
                mma16816(acc[f][j], ah[f], bh);
                mma16816(acc[f][j], ah[f], bl);
                mma16816(acc[f][j], al[f], bh);
            }
        }
    }
}

#define STAGE_HALVES (4*128*72)
#define GEMM_SMEM_BYTES (2*STAGE_HALVES*2)      // double-buffered: 147456 B
#define BD_SMEM_BYTES (STAGE_HALVES*2)

// =====================================================================
// QKV projection, cp.async double-buffered.  Early-exits wasted Q CTAs.
// =====================================================================
__device__ __forceinline__ void qkv_load_stage(__half* S, int r0, int c0, int k0, int t)
{
    __half* Ah = S;
    __half* Al = Ah + 128*72;
    __half* Bh = Al + 128*72;
    __half* Bl = Bh + 128*72;
#pragma unroll
    for (int i = 0; i < 4; i++) {
        int fid = t + i*256;
        int row = fid >> 3, c8 = fid & 7;
        cp16(&Ah[row*72 + c8*8], &g_Inh [(size_t)(r0+row)*512 + k0 + c8*8]);
        cp16(&Al[row*72 + c8*8], &g_Inl [(size_t)(r0+row)*512 + k0 + c8*8]);
        cp16(&Bh[row*72 + c8*8], &g_WqTh[(size_t)(c0+row)*512 + k0 + c8*8]);
        cp16(&Bl[row*72 + c8*8], &g_WqTl[(size_t)(c0+row)*512 + k0 + c8*8]);
    }
}

__global__ __launch_bounds__(256) void qkv_kernel(
    const float* __restrict__ u_emb, const float* __restrict__ v_emb)
{
    extern __shared__ __half smh[];
    int t = threadIdx.x, lane = t & 31, wid = t >> 5;
    int wm = (wid & 3)*32, wn = (wid >> 2)*64;
    int r0 = blockIdx.y*128, c0 = blockIdx.x*128;
    int which0 = c0 >> 9;
    // Q columns are only needed for pos >= MEML: skip pure-memory row blocks
    if (which0 == 0 && (r0 & 1023) < MEML) return;

    float acc[2][8][4];
#pragma unroll
    for (int f = 0; f < 2; f++)
#pragma unroll
        for (int j = 0; j < 8; j++)
#pragma unroll
            for (int e = 0; e < 4; e++) acc[f][j][e] = 0.f;

    qkv_load_stage(smh, r0, c0, 0, t);
    cp_commit();
#pragma unroll
    for (int it = 0; it < 8; it++) {
        __half* cur = smh + (it & 1)*STAGE_HALVES;
        if (it < 7) {
            qkv_load_stage(smh + ((it+1) & 1)*STAGE_HALVES, r0, c0, (it+1)*64, t);
            cp_commit();
            cp_wait<1>();
        } else {
            cp_wait<0>();
        }
        __syncthreads();
        gemm_block_k64(cur, cur + 128*72, cur + 2*128*72, cur + 3*128*72,
                       lane, wm, wn, acc);
        __syncthreads();
    }

    if (which0 == 2) {
        // ---- V block: smem transpose -> coalesced VT stores ----
        __half* Th = smh;                 // [col 128][row 128] stride 136
        __half* Tl = smh + 128*136;
#pragma unroll
        for (int f = 0; f < 2; f++)
#pragma unroll
            for (int j = 0; j < 8; j++)
#pragma unroll
                for (int ii = 0; ii < 2; ii++) {
                    int row = wm + f*16 + (lane >> 2) + ii*8;
                    int colL = wn + j*8 + 2*(lane & 3);
                    float v0 = acc[f][j][2*ii], v1 = acc[f][j][2*ii+1];
                    __half h0, l0, h1, l1;
                    split1h(v0, h0, l0); split1h(v1, h1, l1);
                    Th[colL*136 + row] = h0; Th[(colL+1)*136 + row] = h1;
                    Tl[colL*136 + row] = l0; Tl[(colL+1)*136 + row] = l1;
                }
        __syncthreads();
        int b = r0 >> 10, posbase = r0 & 1023;
        int cpr = c0 - 1024;
#pragma unroll
        for (int i = 0; i < 8; i++) {
            int idx = t + i*256;
            int col = idx >> 4, u8 = idx & 15;
            int cc = cpr + col;
            int h = cc >> 6, d = cc & 63;
            size_t o = (((size_t)(b*NH + h))*DH + d)*TOT + posbase + u8*8;
            *(uint4*)&g_VTh[o] = *(const uint4*)&Th[col*136 + u8*8];
            *(uint4*)&g_VTl[o] = *(const uint4*)&Tl[col*136 + u8*8];
        }
        return;
    }

#pragma unroll
    for (int f = 0; f < 2; f++)
#pragma unroll
        for (int j = 0; j < 8; j++)
#pragma unroll
            for (int ii = 0; ii < 2; ii++) {
                int gr = r0 + wm + f*16 + (lane >> 2) + ii*8;
                int gc = c0 + wn + j*8 + 2*(lane & 3);
                float v0 = acc[f][j][2*ii], v1 = acc[f][j][2*ii+1];
                int b = gr >> 10, pos = gr & 1023;
                int cc = gc & 511;
                int h = cc >> 6, d = cc & 63;
                int bh = b*NH + h;
                if (which0 == 1) {
                    __half2 hh, ll; split2h(v0, v1, hh, ll);
                    size_t idx = ((size_t)bh*TOT + pos)*DH + d;
                    *(__half2*)&g_Kh[idx] = hh; *(__half2*)&g_Kl[idx] = ll;
                } else if (pos >= MEML) {
                    int n = pos - MEML;
                    size_t idx = ((size_t)bh*SEQL + n)*DH + d;
                    __half2 hh, ll;
                    split2h(v0 + u_emb[d], v1 + u_emb[d+1], hh, ll);
                    *(__half2*)&g_QUh[idx] = hh; *(__half2*)&g_QUl[idx] = ll;
                    split2h(v0 + v_emb[d], v1 + v_emb[d+1], hh, ll);
                    *(__half2*)&g_QVh[idx] = hh; *(__half2*)&g_QVl[idx] = ll;
                }
            }
}

// =====================================================================
// krel: Krel[h][s][d] = posenc(s) @ W_rel, split fp16
// =====================================================================
__global__ __launch_bounds__(512) void krel_kernel(const float* __restrict__ Wrel)
{
    __shared__ float R[2*NOCTL];
    int s = blockIdx.x;
    int t = threadIdx.x;
    if (t < NOCTL) {
        float mult = exp2f((float)(t - (NOCTL-1))) * 3.14159265358979323846f;
        float arg = (float)s * mult;
        R[t]         = sinf(arg);
        R[t + NOCTL] = cosf(arg);
    }
    __syncthreads();
    float acc = 0.f;
#pragma unroll
    for (int j = 0; j < 2*NOCTL; j++) acc += R[j] * Wrel[j*INNERD + t];
    int h = t >> 6, d = t & 63;
    __half hh, ll; split1h(acc, hh, ll);
    size_t idx = ((size_t)h*CTXL + s)*DH + d;
    g_Krelh[idx] = hh; g_Krell[idx] = ll;
}

// =====================================================================
// bd: computes QV.Krel^T and stores PRE-SHIFTED: BDs[bh][n][m] at s=MEML+n-m
// =====================================================================
__global__ __launch_bounds__(256) void bd_kernel()
{
    extern __shared__ __half smh[];
    __half* Ah = smh;
    __half* Al = Ah + 128*72;
    __half* Bh = Al + 128*72;
    __half* Bl = Bh + 128*72;
    int t = threadIdx.x, lane = t & 31, wid = t >> 5;
    int wm = (wid & 3)*32, wn = (wid >> 2)*64;
    int bh = blockIdx.z, h = bh & 7;
    int n0 = blockIdx.y*128, s0 = blockIdx.x*128;
    if (s0 > MEML + n0 + 127) return;

    float acc[2][8][4];
#pragma unroll
    for (int f = 0; f < 2; f++)
#pragma unroll
        for (int j = 0; j < 8; j++)
#pragma unroll
            for (int e = 0; e < 4; e++) acc[f][j][e] = 0.f;

#pragma unroll
    for (int i = 0; i < 4; i++) {
        int fid = t + i*256;
        int row = fid >> 3, c8 = fid & 7;
        *(uint4*)&Ah[row*72 + c8*8] = *(const uint4*)&g_QVh[((size_t)bh*SEQL + n0 + row)*DH + c8*8];
        *(uint4*)&Al[row*72 + c8*8] = *(const uint4*)&g_QVl[((size_t)bh*SEQL + n0 + row)*DH + c8*8];
        *(uint4*)&Bh[row*72 + c8*8] = *(const uint4*)&g_Krelh[((size_t)h*CTXL + s0 + row)*DH + c8*8];
        *(uint4*)&Bl[row*72 + c8*8] = *(const uint4*)&g_Krell[((size_t)h*CTXL + s0 + row)*DH + c8*8];
    }
    __syncthreads();
    gemm_block_k64(Ah, Al, Bh, Bl, lane, wm, wn, acc);

#pragma unroll
    for (int f = 0; f < 2; f++)
#pragma unroll
        for (int j = 0; j < 8; j++)
#pragma unroll
            for (int ii = 0; ii < 2; ii++) {
                int n = n0 + wm + f*16 + (lane >> 2) + ii*8;
                int s = s0 + wn + j*8 + 2*(lane & 3);
                int m = MEML + n - s;          // shifted index (m <= 1023 always)
                float* row = g_BDs + ((size_t)bh*SEQL + n)*TOT;
                if (m >= 0)     row[m]   = acc[f][j][2*ii];
                if (m - 1 >= 0) row[m-1] = acc[f][j][2*ii+1];
            }
}

// =====================================================================
// attn: tensor-core flash attention; coalesced shifted-BD reads.
// =====================================================================
#define ATTN_SMEM_BYTES (8*64*72*2)

__global__ __launch_bounds__(128) void attn_kernel()
{
    extern __shared__ __half smh[];
    __half* Qh = smh;
    __half* Ql = Qh + 64*72;
    __half* Kh = Ql + 64*72;
    __half* Kl = Kh + 64*72;
    __half* Vh = Kl + 64*72;
    __half* Vl = Vh + 64*72;
    __half* Ph = Vl + 64*72;
    __half* Pl = Ph + 64*72;

    int t = threadIdx.x, lane = t & 31, wq = t >> 5;
    int bh = blockIdx.y, b = bh >> 3, h = bh & 7;
    int n0 = blockIdx.x * 64;

#pragma unroll
    for (int i = 0; i < 4; i++) {
        int fid = t + i*128;
        int row = fid >> 3, c8 = fid & 7;
        *(uint4*)&Qh[row*72 + c8*8] = *(const uint4*)&g_QUh[((size_t)bh*SEQL + n0 + row)*DH + c8*8];
        *(uint4*)&Ql[row*72 + c8*8] = *(const uint4*)&g_QUl[((size_t)bh*SEQL + n0 + row)*DH + c8*8];
    }

    float O[8][4];
#pragma unroll
    for (int j = 0; j < 8; j++)
#pragma unroll
        for (int e = 0; e < 4; e++) O[j][e] = 0.f;
    float M[2] = {-1e30f, -1e30f}, L[2] = {0.f, 0.f};

    int rl0 = wq*16 + (lane >> 2);
    int c0j = 2*(lane & 3);
    const float* BDr0 = g_BDs + ((size_t)bh*SEQL + (n0 + rl0))*TOT;
    const float* BDr1 = BDr0 + 8*(size_t)TOT;
    int lim0 = MEML + n0 + rl0, lim1 = lim0 + 8;

    int ntiles = (MEML + n0 + 63)/64 + 1;
    for (int tile = 0; tile < ntiles; tile++) {
        int m0 = tile*64;
        __syncthreads();
#pragma unroll
        for (int i = 0; i < 4; i++) {
            int fid = t + i*128;
            int row = fid >> 3, c8 = fid & 7;
            *(uint4*)&Kh[row*72 + c8*8] = *(const uint4*)&g_Kh[((size_t)bh*TOT + m0 + row)*DH + c8*8];
            *(uint4*)&Kl[row*72 + c8*8] = *(const uint4*)&g_Kl[((size_t)bh*TOT + m0 + row)*DH + c8*8];
            *(uint4*)&Vh[row*72 + c8*8] = *(const uint4*)&g_VTh[((size_t)bh*DH + row)*TOT + m0 + c8*8];
            *(uint4*)&Vl[row*72 + c8*8] = *(const uint4*)&g_VTl[((size_t)bh*DH + row)*TOT + m0 + c8*8];
        }
        __syncthreads();

        // ---- S = Q . K^T ----
        float S[8][4];
#pragma unroll
        for (int j = 0; j < 8; j++)
#pragma unroll
            for (int e = 0; e < 4; e++) S[j][e] = 0.f;
#pragma unroll
        for (int kb = 0; kb < 64; kb += 16) {
            int cA = kb + c0j;
            int r = wq*16 + (lane >> 2);
            unsigned ah[4], al[4];
            ah[0] = *(const unsigned*)&Qh[r*72 + cA];
            ah[1] = *(const unsigned*)&Qh[(r+8)*72 + cA];
            ah[2] = *(const unsigned*)&Qh[r*72 + cA + 8];
            ah[3] = *(const unsigned*)&Qh[(r+8)*72 + cA + 8];
            al[0] = *(const unsigned*)&Ql[r*72 + cA];
            al[1] = *(const unsigned*)&Ql[(r+8)*72 + cA];
            al[2] = *(const unsigned*)&Ql[r*72 + cA + 8];
            al[3] = *(const unsigned*)&Ql[(r+8)*72 + cA + 8];
#pragma unroll
            for (int j = 0; j < 8; j++) {
                int n = j*8 + (lane >> 2);
                unsigned bhf[2], blf[2];
                bhf[0] = *(const unsigned*)&Kh[n*72 + cA];
                bhf[1] = *(const unsigned*)&Kh[n*72 + cA + 8];
                blf[0] = *(const unsigned*)&Kl[n*72 + cA];
                blf[1] = *(const unsigned*)&Kl[n*72 + cA + 8];
                mma16816(S[j], ah, bhf);
                mma16816(S[j], ah, blf);
                mma16816(S[j], al, bhf);
            }
        }

        // ---- shifted-BD add (coalesced) + mask + online softmax ----
#pragma unroll
        for (int i = 0; i < 2; i++) {
            const float* BD = i ? BDr1 : BDr0;
            int lim = i ? lim1 : lim0;
            float mx = -1e30f;
#pragma unroll
            for (int j = 0; j < 8; j++) {
                int m = m0 + j*8 + c0j;
                float2 bd = *(const float2*)&BD[m];
                float v0 = (m   <= lim) ? (S[j][2*i]   + bd.x)*0.125f : -1e30f;
                float v1 = (m+1 <= lim) ? (S[j][2*i+1] + bd.y)*0.125f : -1e30f;
                S[j][2*i] = v0; S[j][2*i+1] = v1;
                mx = fmaxf(mx, fmaxf(v0, v1));
            }
            mx = fmaxf(mx, __shfl_xor_sync(0xffffffffu, mx, 1));
            mx = fmaxf(mx, __shfl_xor_sync(0xffffffffu, mx, 2));
            float Mn = fmaxf(M[i], mx);
            float alpha = __expf(M[i] - Mn);
            M[i] = Mn;
            float sum = 0.f;
            int rl = rl0 + 8*i;
#pragma unroll
            for (int j = 0; j < 8; j++) {
                float p0 = __expf(S[j][2*i]   - Mn);
                float p1 = __expf(S[j][2*i+1] - Mn);
                sum += p0 + p1;
                __half2 hh, ll; split2h(p0, p1, hh, ll);
                *(__half2*)&Ph[rl*72 + j*8 + c0j] = hh;
                *(__half2*)&Pl[rl*72 + j*8 + c0j] = ll;
                O[j][2*i] *= alpha; O[j][2*i+1] *= alpha;
            }
            sum += __shfl_xor_sync(0xffffffffu, sum, 1);
            sum += __shfl_xor_sync(0xffffffffu, sum, 2);
            L[i] = L[i]*alpha + sum;
        }
        __syncwarp();

        // ---- O += P . V ----
#pragma unroll
        for (int kb = 0; kb < 64; kb += 16) {
            int cA = kb + c0j;
            int r = wq*16 + (lane >> 2);
            unsigned ah[4], al[4];
            ah[0] = *(const unsigned*)&Ph[r*72 + cA];
            ah[1] = *(const unsigned*)&Ph[(r+8)*72 + cA];
            ah[2] = *(const unsigned*)&Ph[r*72 + cA + 8];
            ah[3] = *(const unsigned*)&Ph[(r+8)*72 + cA + 8];
            al[0] = *(const unsigned*)&Pl[r*72 + cA];
            al[1] = *(const unsigned*)&Pl[(r+8)*72 + cA];
            al[2] = *(const unsigned*)&Pl[r*72 + cA + 8];
            al[3] = *(const unsigned*)&Pl[(r+8)*72 + cA + 8];
#pragma unroll
            for (int j = 0; j < 8; j++) {
                int n = j*8 + (lane >> 2);
                unsigned bhf[2], blf[2];
                bhf[0] = *(const unsigned*)&Vh[n*72 + cA];
                bhf[1] = *(const unsigned*)&Vh[n*72 + cA + 8];
                blf[0] = *(const unsigned*)&Vl[n*72 + cA];
                blf[1] = *(const unsigned*)&Vl[n*72 + cA + 8];
                mma16816(O[j], ah, bhf);
                mma16816(O[j], ah, blf);
                mma16816(O[j], al, bhf);
            }
        }
    }

#pragma unroll
    for (int i = 0; i < 2; i++) {
        float inv = 1.f / L[i];
        int row = b*SEQL + n0 + rl0 + 8*i;
#pragma unroll
        for (int j = 0; j < 8; j++) {
            float o0 = O[j][2*i]*inv, o1 = O[j][2*i+1]*inv;
            __half2 hh, ll; split2h(o0, o1, hh, ll);
            size_t idx = (size_t)row*INNERD + h*DH + j*8 + c0j;
            *(__half2*)&g_AOh[idx] = hh; *(__half2*)&g_AOl[idx] = ll;
        }
    }
}

// =====================================================================
// out: [2048x512] = AO @ W_out + b_out, cp.async double-buffered
// =====================================================================
__device__ __forceinline__ void out_load_stage(__half* S, int r0, int c0, int k0, int t)
{
    __half* Ah = S;
    __half* Al = Ah + 128*72;
    __half* Bh = Al + 128*72;
    __half* Bl = Bh + 128*72;
#pragma unroll
    for (int i = 0; i < 4; i++) {
        int fid = t + i*256;
        int row = fid >> 3, c8 = fid & 7;
        cp16(&Ah[row*72 + c8*8], &g_AOh [(size_t)(r0+row)*512 + k0 + c8*8]);
        cp16(&Al[row*72 + c8*8], &g_AOl [(size_t)(r0+row)*512 + k0 + c8*8]);
        cp16(&Bh[row*72 + c8*8], &g_WoTh[(size_t)(c0+row)*512 + k0 + c8*8]);
        cp16(&Bl[row*72 + c8*8], &g_WoTl[(size_t)(c0+row)*512 + k0 + c8*8]);
    }
}

__global__ __launch_bounds__(256) void out_kernel(
    const float* __restrict__ bias, float* __restrict__ out)
{
    extern __shared__ __half smh[];
    int t = threadIdx.x, lane = t & 31, wid = t >> 5;
    int wm = (wid & 3)*32, wn = (wid >> 2)*64;
    int r0 = blockIdx.y*128, c0 = blockIdx.x*128;

    float acc[2][8][4];
#pragma unroll
    for (int f = 0; f < 2; f++)
#pragma unroll
        for (int j = 0; j < 8; j++)
#pragma unroll
            for (int e = 0; e < 4; e++) acc[f][j][e] = 0.f;

    out_load_stage(smh, r0, c0, 0, t);
    cp_commit();
#pragma unroll
    for (int it = 0; it < 8; it++) {
        __half* cur = smh + (it & 1)*STAGE_HALVES;
        if (it < 7) {
            out_load_stage(smh + ((it+1) & 1)*STAGE_HALVES, r0, c0, (it+1)*64, t);
            cp_commit();
            cp_wait<1>();
        } else {
            cp_wait<0>();
        }
        __syncthreads();
        gemm_block_k64(cur, cur + 128*72, cur + 2*128*72, cur + 3*128*72,
                       lane, wm, wn, acc);
        __syncthreads();
    }

#pragma unroll
    for (int f = 0; f < 2; f++)
#pragma unroll
        for (int j = 0; j < 8; j++)
#pragma unroll
            for (int ii = 0; ii < 2; ii++) {
                int gr = r0 + wm + f*16 + (lane >> 2) + ii*8;
                int gc = c0 + wn + j*8 + 2*(lane & 3);
                *(float2*)&out[(size_t)gr*DIMM + gc] =
                    make_float2(acc[f][j][2*ii] + bias[gc], acc[f][j][2*ii+1] + bias[gc+1]);
            }
}

// =====================================================================
extern "C" void kernel_launch(void* const* d_in, const int* in_sizes, int n_in,
                              void* d_out, int out_size)
{
    const float* x      = (const float*)d_in[0];
    const float* memory = (const float*)d_in[1];
    const float* Wqkv   = (const float*)d_in[2];
    const float* Wrel   = (const float*)d_in[3];
    const float* Wout   = (const float*)d_in[4];
    const float* bout   = (const float*)d_in[5];
    const float* u_emb  = (const float*)d_in[6];
    const float* v_emb  = (const float*)d_in[7];
    float* out = (float*)d_out;
    (void)in_sizes; (void)n_in; (void)out_size;

    cudaFuncSetAttribute(qkv_kernel,  cudaFuncAttributeMaxDynamicSharedMemorySize, GEMM_SMEM_BYTES);
    cudaFuncSetAttribute(bd_kernel,   cudaFuncAttributeMaxDynamicSharedMemorySize, BD_SMEM_BYTES);
    cudaFuncSetAttribute(out_kernel,  cudaFuncAttributeMaxDynamicSharedMemorySize, GEMM_SMEM_BYTES);
    cudaFuncSetAttribute(attn_kernel, cudaFuncAttributeMaxDynamicSharedMemorySize, ATTN_SMEM_BYTES);

    pre_in_kernel<<<8192*512/4/256, 256>>>(x, memory);
    pre_w_kernel<<<dim3(1536/64, 512/64), 256>>>(Wqkv, 1536, 0);
    pre_w_kernel<<<dim3(512/64, 512/64), 256>>>(Wout, 512, 1);
    krel_kernel<<<CTXL, 512>>>(Wrel);
    qkv_kernel<<<dim3(1536/128, 8192/128), 256, GEMM_SMEM_BYTES>>>(u_emb, v_emb);
    bd_kernel<<<dim3(CTXL/128, SEQL/128, BB*NH), 256, BD_SMEM_BYTES>>>();
    attn_kernel<<<dim3(SEQL/64, BB*NH), 128, ATTN_SMEM_BYTES>>>();
    out_kernel<<<dim3(DIMM/128, 2048/128), 256, GEMM_SMEM_BYTES>>>(bout, out);
}